// round 3
// baseline (speedup 1.0000x reference)
#include <cuda_runtime.h>
#include <cstdint>
#include <math.h>

// Problem constants
#define SEQ   4096
#define BATCH 8
#define DIMN  1024
#define TOK   (SEQ * BATCH)                 // 32768 rows
static const size_t NELEM = (size_t)TOK * DIMN;

// ---------------- scratch (device globals; no allocation allowed) ----------
__device__ float g_inp   [(size_t)TOK * DIMN];
__device__ float g_gate  [(size_t)TOK * DIMN];
__device__ float g_w     [(size_t)TOK * DIMN];
__device__ float g_u     [(size_t)TOK * DIMN];   // becomes v after ADDC GEMM
__device__ float g_states[(size_t)TOK * DIMN];   // [t][b][d]
__device__ unsigned long long g_bar;

// ---------------- f32x2 helpers (FFMA2 only reachable via PTX) -------------
__device__ __forceinline__ unsigned long long dup2(float x) {
    unsigned long long r;
    asm("mov.b64 %0, {%1, %1};" : "=l"(r) : "r"(__float_as_uint(x)));
    return r;
}
__device__ __forceinline__ unsigned long long fma2(unsigned long long a,
                                                   unsigned long long b,
                                                   unsigned long long c) {
    unsigned long long d;
    asm("fma.rn.f32x2 %0, %1, %2, %3;" : "=l"(d) : "l"(a), "l"(b), "l"(c));
    return d;
}
__device__ __forceinline__ float lo32(unsigned long long v) { return __uint_as_float((unsigned)v); }
__device__ __forceinline__ float hi32(unsigned long long v) { return __uint_as_float((unsigned)(v >> 32)); }

// ---------------- GEMM:  C[m][n] = sum_k X[m][k] * W[n][k]  (+ epilogue) ---
// M = 32768, N = K = 1024. Tiles 128x128x16, 256 threads, 8x8 microtile.
#define MODE_PLAIN 0
#define MODE_SIGW  1   // C = sigmoid(acc+bias); C2 = (1-C)*aux   (gate & w)
#define MODE_ADDC  2   // C += acc                                (v = w@A^T + u)
#define MODE_OUTP  3   // permuted store: row m=(t*8+b) -> out[(b*SEQ+t)][n]

template <int MODE>
__global__ void __launch_bounds__(256, 2)
gemm_tn(const float* __restrict__ X, const float* __restrict__ Wm,
        const float* __restrict__ bias, const float* __restrict__ aux,
        float* __restrict__ C, float* __restrict__ C2)
{
    __shared__ float Xs[16][132];
    __shared__ float Ws[16][132];

    const int tid  = threadIdx.x;
    const int bn   = blockIdx.x;      // 0..7
    const int bm   = blockIdx.y;      // 0..255
    const int row0 = bm * 128;
    const int col0 = bn * 128;
    const int r0   = tid >> 2;        // 0..63
    const int kq   = tid & 3;         // 0..3
    const int tx   = tid & 15;
    const int ty   = tid >> 4;

    const float* xp0 = X  + (size_t)(row0 + r0)      * DIMN + kq * 4;
    const float* xp1 = X  + (size_t)(row0 + r0 + 64) * DIMN + kq * 4;
    const float* wp0 = Wm + (size_t)(col0 + r0)      * DIMN + kq * 4;
    const float* wp1 = Wm + (size_t)(col0 + r0 + 64) * DIMN + kq * 4;

    float4 xa0 = *(const float4*)xp0;
    float4 xa1 = *(const float4*)xp1;
    float4 wa0 = *(const float4*)wp0;
    float4 wa1 = *(const float4*)wp1;

    unsigned long long acc[8][4];
#pragma unroll
    for (int i = 0; i < 8; i++)
#pragma unroll
        for (int j = 0; j < 4; j++) acc[i][j] = 0ull;

    for (int kt = 0; kt < 64; kt++) {
        // stage registers -> smem (transposed: [k][m] / [k][n])
        Xs[kq*4+0][r0]    = xa0.x; Xs[kq*4+1][r0]    = xa0.y;
        Xs[kq*4+2][r0]    = xa0.z; Xs[kq*4+3][r0]    = xa0.w;
        Xs[kq*4+0][r0+64] = xa1.x; Xs[kq*4+1][r0+64] = xa1.y;
        Xs[kq*4+2][r0+64] = xa1.z; Xs[kq*4+3][r0+64] = xa1.w;
        Ws[kq*4+0][r0]    = wa0.x; Ws[kq*4+1][r0]    = wa0.y;
        Ws[kq*4+2][r0]    = wa0.z; Ws[kq*4+3][r0]    = wa0.w;
        Ws[kq*4+0][r0+64] = wa1.x; Ws[kq*4+1][r0+64] = wa1.y;
        Ws[kq*4+2][r0+64] = wa1.z; Ws[kq*4+3][r0+64] = wa1.w;
        __syncthreads();

        if (kt < 63) {   // prefetch next k-tile into registers (hides gmem latency)
            xa0 = *(const float4*)(xp0 + (kt + 1) * 16);
            xa1 = *(const float4*)(xp1 + (kt + 1) * 16);
            wa0 = *(const float4*)(wp0 + (kt + 1) * 16);
            wa1 = *(const float4*)(wp1 + (kt + 1) * 16);
        }

#pragma unroll
        for (int k = 0; k < 16; k++) {
            float4 a0 = *(const float4*)&Xs[k][ty * 8];
            float4 a1 = *(const float4*)&Xs[k][ty * 8 + 4];
            ulonglong2 bq0 = *(const ulonglong2*)&Ws[k][tx * 8];
            ulonglong2 bq1 = *(const ulonglong2*)&Ws[k][tx * 8 + 4];
            unsigned long long bb0 = bq0.x, bb1 = bq0.y, bb2 = bq1.x, bb3 = bq1.y;
            float aa[8] = {a0.x, a0.y, a0.z, a0.w, a1.x, a1.y, a1.z, a1.w};
#pragma unroll
            for (int mi = 0; mi < 8; mi++) {
                unsigned long long am = dup2(aa[mi]);
                acc[mi][0] = fma2(am, bb0, acc[mi][0]);
                acc[mi][1] = fma2(am, bb1, acc[mi][1]);
                acc[mi][2] = fma2(am, bb2, acc[mi][2]);
                acc[mi][3] = fma2(am, bb3, acc[mi][3]);
            }
        }
        __syncthreads();
    }

    // epilogue
#pragma unroll
    for (int mi = 0; mi < 8; mi++) {
        const int m = row0 + ty * 8 + mi;
#pragma unroll
        for (int p = 0; p < 4; p++) {
            const int col = col0 + tx * 8 + p * 2;
            float v0 = lo32(acc[mi][p]);
            float v1 = hi32(acc[mi][p]);
            if (MODE == MODE_PLAIN) {
                if (bias) { v0 += bias[col]; v1 += bias[col + 1]; }
                *(float2*)&C[(size_t)m * DIMN + col] = make_float2(v0, v1);
            } else if (MODE == MODE_SIGW) {
                v0 += bias[col]; v1 += bias[col + 1];
                float s0 = 1.0f / (1.0f + expf(-v0));
                float s1 = 1.0f / (1.0f + expf(-v1));
                const size_t idx = (size_t)m * DIMN + col;
                *(float2*)&C[idx] = make_float2(s0, s1);
                float2 iv = *(const float2*)&aux[idx];
                *(float2*)&C2[idx] = make_float2((1.0f - s0) * iv.x, (1.0f - s1) * iv.y);
            } else if (MODE == MODE_ADDC) {
                const size_t idx = (size_t)m * DIMN + col;
                float2 old = *(const float2*)&C[idx];
                *(float2*)&C[idx] = make_float2(old.x + v0, old.y + v1);
            } else {  // MODE_OUTP
                const int tt = m >> 3, bb = m & 7;
                v0 += bias[col]; v1 += bias[col + 1];
                const size_t idx = ((size_t)bb * SEQ + tt) * DIMN + col;
                *(float2*)&C[idx] = make_float2(v0, v1);
            }
        }
    }
}

// ---------------- grid-barrier reset (runs before scan each launch) --------
__global__ void bar_reset_kernel() { g_bar = 0ull; }

// ---------------- persistent scan kernel -----------------------------------
// G=128 CTAs (<=148 SMs -> all co-resident). CTA g owns A rows [g*8, g*8+8).
// Per step: bl[b][d] = gate[t][b][d]*state[t-1][b][d] (full, in smem);
// out[e][b] = tanh( dot(A[e], bl[b]) + v[t][b][e] ).
#define GBLK 128

__global__ void __launch_bounds__(256, 1)
scan_kernel(const float* __restrict__ gate, const float* __restrict__ v,
            float* __restrict__ states, const float* __restrict__ A)
{
    extern __shared__ float sm[];
    float* As  = sm;                 // [8][1028]
    float* bl  = sm + 8 * 1028;      // [8][1028]
    float* red = sm + 16 * 1028;     // [256]

    const int tid = threadIdx.x;
    const int g   = blockIdx.x;

    // Load this block's A slice into smem (padded rows: 1028 floats)
    {
        const float* Ap = A + (size_t)g * 8 * DIMN;
        for (int i = tid * 4; i < 8 * DIMN; i += 256 * 4) {
            const int e = i >> 10, d = i & 1023;
            float4 val = *(const float4*)&Ap[(size_t)e * DIMN + d];
            *(float4*)&As[e * 1028 + d] = val;
        }
    }

    const int b_o = tid & 7;           // batch
    const int e_o = (tid >> 3) & 7;    // local e row
    const int kq  = tid >> 6;          // k-quarter (0..3), 256 d's each

    float4 pg[8];                      // prefetched gate[t] (filled at end of t-1)
    float  pv = 0.0f;                  // prefetched v[t][b_o][g*8+e_o]
    if (tid < 64)
        pv = v[((size_t)b_o * SEQ + 0) * DIMN + g * 8 + e_o];

    __syncthreads();

    for (int t = 0; t < SEQ; t++) {
        // ---- phase 1: bl = gate_t * state_{t-1}  (state_{-1} = 0)
        if (t == 0) {
#pragma unroll
            for (int j = 0; j < 8; j++)
                *(float4*)&bl[j * 1028 + tid * 4] = make_float4(0.f, 0.f, 0.f, 0.f);
        } else {
#pragma unroll
            for (int j = 0; j < 8; j++) {
                float4 s4 = *(const float4*)&states[(size_t)(t - 1) * (BATCH * DIMN)
                                                    + j * DIMN + tid * 4];
                float4 gq = pg[j];
                *(float4*)&bl[j * 1028 + tid * 4] =
                    make_float4(gq.x * s4.x, gq.y * s4.y, gq.z * s4.z, gq.w * s4.w);
            }
        }
        __syncthreads();

        // ---- phase 2: partial dot over this thread's 256 d's
        unsigned long long a0 = 0ull, a1 = 0ull;
        const float* ap = &As[e_o * 1028 + kq * 256];
        const float* xp = &bl[b_o * 1028 + kq * 256];
#pragma unroll 8
        for (int j = 0; j < 64; j++) {
            ulonglong2 av = *(const ulonglong2*)(ap + j * 4);
            ulonglong2 xv = *(const ulonglong2*)(xp + j * 4);
            a0 = fma2(av.x, xv.x, a0);
            a1 = fma2(av.y, xv.y, a1);
        }
        red[tid] = lo32(a0) + hi32(a0) + lo32(a1) + hi32(a1);
        __syncthreads();

        // ---- phase 3: combine k-quarters, add v, tanh, write state
        if (tid < 64) {
            float tot = red[tid] + red[tid + 64] + red[tid + 128] + red[tid + 192];
            float val = tanhf(tot + pv);
            states[(size_t)t * (BATCH * DIMN) + b_o * DIMN + g * 8 + e_o] = val;
        }

        // ---- prefetch next step's gate/v while waiting at the barrier
        if (t + 1 < SEQ) {
#pragma unroll
            for (int j = 0; j < 8; j++)
                pg[j] = *(const float4*)&gate[((size_t)j * SEQ + (t + 1)) * DIMN + tid * 4];
            if (tid < 64)
                pv = v[((size_t)b_o * SEQ + (t + 1)) * DIMN + g * 8 + e_o];

            // ---- grid barrier (monotone u64 counter, zeroed by bar_reset)
            __syncthreads();
            if (tid == 0) {
                __threadfence();
                atomicAdd(&g_bar, 1ULL);
                const unsigned long long target = (unsigned long long)(t + 1) * GBLK;
                while (*(volatile unsigned long long*)&g_bar < target) {}
                __threadfence();
            }
            __syncthreads();
        }
    }
}

// ---------------- host launcher --------------------------------------------
extern "C" void kernel_launch(void* const* d_in, const int* in_sizes, int n_in,
                              void* d_out, int out_size)
{
    (void)in_sizes; (void)n_in; (void)out_size;

    const float* x     = (const float*)d_in[0];
    const float* A     = (const float*)d_in[1];
    const float* B     = (const float*)d_in[2];
    const float* W_in  = (const float*)d_in[3];
    const float* b_in  = (const float*)d_in[4];
    const float* W_g   = (const float*)d_in[5];
    const float* b_g   = (const float*)d_in[6];
    const float* W_out = (const float*)d_in[7];
    const float* b_out = (const float*)d_in[8];
    float* out = (float*)d_out;

    float *inp, *gate, *w, *u, *states;
    cudaGetSymbolAddress((void**)&inp,    g_inp);
    cudaGetSymbolAddress((void**)&gate,   g_gate);
    cudaGetSymbolAddress((void**)&w,      g_w);
    cudaGetSymbolAddress((void**)&u,      g_u);
    cudaGetSymbolAddress((void**)&states, g_states);

    const int scan_smem = (16 * 1028 + 256) * (int)sizeof(float);  // 66816 B
    cudaFuncSetAttribute(scan_kernel, cudaFuncAttributeMaxDynamicSharedMemorySize,
                         scan_smem);

    dim3 grid(8, 256), blk(256);

    // 1) inp = x @ W_in^T + b_in
    gemm_tn<MODE_PLAIN><<<grid, blk>>>(x, W_in, b_in, nullptr, inp, nullptr);
    // 2) u = inp @ B^T
    gemm_tn<MODE_PLAIN><<<grid, blk>>>(inp, B, nullptr, nullptr, u, nullptr);
    // 3) gate = sigmoid(inp @ W_gate^T + b_gate);  w = (1-gate)*inp
    gemm_tn<MODE_SIGW ><<<grid, blk>>>(inp, W_g, b_g, inp, gate, w);
    // 4) u += w @ A^T   (now u == v)
    gemm_tn<MODE_ADDC ><<<grid, blk>>>(w, A, nullptr, nullptr, u, nullptr);
    // 5) sequential scan
    bar_reset_kernel<<<1, 1>>>();
    scan_kernel<<<GBLK, blk, scan_smem>>>(gate, u, states, A);
    // 6) out = states @ W_out^T + b_out  (permuted store to (b, s, e))
    gemm_tn<MODE_OUTP><<<grid, blk>>>(states, W_out, b_out, nullptr, out, nullptr);
}

// round 4
// speedup vs baseline: 1.0496x; 1.0496x over previous
#include <cuda_runtime.h>
#include <cstdint>
#include <math.h>

// Problem constants
#define SEQ   4096
#define BATCH 8
#define DIMN  1024
#define TOK   (SEQ * BATCH)                 // 32768 rows

// ---------------- scratch (device globals; no allocation allowed) ----------
__device__ float g_inp   [(size_t)TOK * DIMN];
__device__ float g_gate  [(size_t)TOK * DIMN];
__device__ float g_w     [(size_t)TOK * DIMN];
__device__ float g_u     [(size_t)TOK * DIMN];   // becomes v after ADDC GEMM
__device__ float g_states[(size_t)TOK * DIMN];   // [t][b][d]
__device__ float g_bl    [2 * BATCH * DIMN];     // blended, double-buffered by parity
__device__ unsigned long long g_bar;

// ---------------- f32x2 helpers (FFMA2 only reachable via PTX) -------------
__device__ __forceinline__ unsigned long long dup2(float x) {
    unsigned long long r;
    asm("mov.b64 %0, {%1, %1};" : "=l"(r) : "r"(__float_as_uint(x)));
    return r;
}
__device__ __forceinline__ unsigned long long fma2(unsigned long long a,
                                                   unsigned long long b,
                                                   unsigned long long c) {
    unsigned long long d;
    asm("fma.rn.f32x2 %0, %1, %2, %3;" : "=l"(d) : "l"(a), "l"(b), "l"(c));
    return d;
}
__device__ __forceinline__ float lo32(unsigned long long v) { return __uint_as_float((unsigned)v); }
__device__ __forceinline__ float hi32(unsigned long long v) { return __uint_as_float((unsigned)(v >> 32)); }

// ---------------- fence-free barrier primitives ----------------------------
// release-atomic arrival: orders prior (write-through) global stores without
// the CCTL.IVALL that a gpu-scope fence would emit.
__device__ __forceinline__ void arrive_release(unsigned long long* p) {
    asm volatile("red.release.gpu.global.add.u64 [%0], 1;" :: "l"(p) : "memory");
}
__device__ __forceinline__ unsigned long long ld_acquire(const unsigned long long* p) {
    unsigned long long v;
    asm volatile("ld.acquire.gpu.global.u64 %0, [%1];" : "=l"(v) : "l"(p) : "memory");
    return v;
}

// ---------------- GEMM:  C[m][n] = sum_k X[m][k] * W[n][k]  (+ epilogue) ---
// M = 32768, N = K = 1024. Tiles 128x128x16, 256 threads, 8x8 microtile.
#define MODE_PLAIN 0
#define MODE_SIGW  1   // C = sigmoid(acc+bias); C2 = (1-C)*aux   (gate & w)
#define MODE_ADDC  2   // C += acc                                (v = w@A^T + u)
#define MODE_OUTP  3   // permuted store: row m=(t*8+b) -> out[(b*SEQ+t)][n]

template <int MODE>
__global__ void __launch_bounds__(256, 2)
gemm_tn(const float* __restrict__ X, const float* __restrict__ Wm,
        const float* __restrict__ bias, const float* __restrict__ aux,
        float* __restrict__ C, float* __restrict__ C2)
{
    __shared__ float Xs[16][132];
    __shared__ float Ws[16][132];

    const int tid  = threadIdx.x;
    const int bn   = blockIdx.x;      // 0..7
    const int bm   = blockIdx.y;      // 0..255
    const int row0 = bm * 128;
    const int col0 = bn * 128;
    const int r0   = tid >> 2;        // 0..63
    const int kq   = tid & 3;         // 0..3
    const int tx   = tid & 15;
    const int ty   = tid >> 4;

    const float* xp0 = X  + (size_t)(row0 + r0)      * DIMN + kq * 4;
    const float* xp1 = X  + (size_t)(row0 + r0 + 64) * DIMN + kq * 4;
    const float* wp0 = Wm + (size_t)(col0 + r0)      * DIMN + kq * 4;
    const float* wp1 = Wm + (size_t)(col0 + r0 + 64) * DIMN + kq * 4;

    float4 xa0 = *(const float4*)xp0;
    float4 xa1 = *(const float4*)xp1;
    float4 wa0 = *(const float4*)wp0;
    float4 wa1 = *(const float4*)wp1;

    unsigned long long acc[8][4];
#pragma unroll
    for (int i = 0; i < 8; i++)
#pragma unroll
        for (int j = 0; j < 4; j++) acc[i][j] = 0ull;

    for (int kt = 0; kt < 64; kt++) {
        Xs[kq*4+0][r0]    = xa0.x; Xs[kq*4+1][r0]    = xa0.y;
        Xs[kq*4+2][r0]    = xa0.z; Xs[kq*4+3][r0]    = xa0.w;
        Xs[kq*4+0][r0+64] = xa1.x; Xs[kq*4+1][r0+64] = xa1.y;
        Xs[kq*4+2][r0+64] = xa1.z; Xs[kq*4+3][r0+64] = xa1.w;
        Ws[kq*4+0][r0]    = wa0.x; Ws[kq*4+1][r0]    = wa0.y;
        Ws[kq*4+2][r0]    = wa0.z; Ws[kq*4+3][r0]    = wa0.w;
        Ws[kq*4+0][r0+64] = wa1.x; Ws[kq*4+1][r0+64] = wa1.y;
        Ws[kq*4+2][r0+64] = wa1.z; Ws[kq*4+3][r0+64] = wa1.w;
        __syncthreads();

        if (kt < 63) {
            xa0 = *(const float4*)(xp0 + (kt + 1) * 16);
            xa1 = *(const float4*)(xp1 + (kt + 1) * 16);
            wa0 = *(const float4*)(wp0 + (kt + 1) * 16);
            wa1 = *(const float4*)(wp1 + (kt + 1) * 16);
        }

#pragma unroll
        for (int k = 0; k < 16; k++) {
            float4 a0 = *(const float4*)&Xs[k][ty * 8];
            float4 a1 = *(const float4*)&Xs[k][ty * 8 + 4];
            ulonglong2 bq0 = *(const ulonglong2*)&Ws[k][tx * 8];
            ulonglong2 bq1 = *(const ulonglong2*)&Ws[k][tx * 8 + 4];
            unsigned long long bb0 = bq0.x, bb1 = bq0.y, bb2 = bq1.x, bb3 = bq1.y;
            float aa[8] = {a0.x, a0.y, a0.z, a0.w, a1.x, a1.y, a1.z, a1.w};
#pragma unroll
            for (int mi = 0; mi < 8; mi++) {
                unsigned long long am = dup2(aa[mi]);
                acc[mi][0] = fma2(am, bb0, acc[mi][0]);
                acc[mi][1] = fma2(am, bb1, acc[mi][1]);
                acc[mi][2] = fma2(am, bb2, acc[mi][2]);
                acc[mi][3] = fma2(am, bb3, acc[mi][3]);
            }
        }
        __syncthreads();
    }

#pragma unroll
    for (int mi = 0; mi < 8; mi++) {
        const int m = row0 + ty * 8 + mi;
#pragma unroll
        for (int p = 0; p < 4; p++) {
            const int col = col0 + tx * 8 + p * 2;
            float v0 = lo32(acc[mi][p]);
            float v1 = hi32(acc[mi][p]);
            if (MODE == MODE_PLAIN) {
                if (bias) { v0 += bias[col]; v1 += bias[col + 1]; }
                *(float2*)&C[(size_t)m * DIMN + col] = make_float2(v0, v1);
            } else if (MODE == MODE_SIGW) {
                v0 += bias[col]; v1 += bias[col + 1];
                float s0 = 1.0f / (1.0f + expf(-v0));
                float s1 = 1.0f / (1.0f + expf(-v1));
                const size_t idx = (size_t)m * DIMN + col;
                *(float2*)&C[idx] = make_float2(s0, s1);
                float2 iv = *(const float2*)&aux[idx];
                *(float2*)&C2[idx] = make_float2((1.0f - s0) * iv.x, (1.0f - s1) * iv.y);
            } else if (MODE == MODE_ADDC) {
                const size_t idx = (size_t)m * DIMN + col;
                float2 old = *(const float2*)&C[idx];
                *(float2*)&C[idx] = make_float2(old.x + v0, old.y + v1);
            } else {  // MODE_OUTP
                const int tt = m >> 3, bb = m & 7;
                v0 += bias[col]; v1 += bias[col + 1];
                const size_t idx = ((size_t)bb * SEQ + tt) * DIMN + col;
                *(float2*)&C[idx] = make_float2(v0, v1);
            }
        }
    }
}

// ---------------- grid-barrier reset (runs before scan each launch) --------
__global__ void bar_reset_kernel() { g_bar = 0ull; }

// ---------------- persistent scan kernel -----------------------------------
// G=128 CTAs (all co-resident). CTA g owns A rows [g*8, g*8+8).
// Producer-side gating: at step t, after computing state_t for its (e,b)
// cells, CTA g publishes blended_{t+1} = gate_{t+1} * state_t for those cells
// into the parity-(t+1) buffer. Consumers read only blended (32 KB/step).
#define GBLK 128

__global__ void __launch_bounds__(256, 1)
scan_kernel(const float* __restrict__ gate, const float* __restrict__ v,
            float* __restrict__ states, const float* __restrict__ A,
            float* __restrict__ blended)
{
    extern __shared__ float sm[];
    float* As  = sm;                 // [8][1028]
    float* bl  = sm + 8 * 1028;      // [8][1028]
    float* red = sm + 16 * 1028;     // [256]

    const int tid = threadIdx.x;
    const int g   = blockIdx.x;

    // Load this block's A slice into smem (padded rows: 1028 floats)
    {
        const float* Ap = A + (size_t)g * 8 * DIMN;
        for (int i = tid * 4; i < 8 * DIMN; i += 256 * 4) {
            const int e = i >> 10, d = i & 1023;
            float4 val = *(const float4*)&Ap[(size_t)e * DIMN + d];
            *(float4*)&As[e * 1028 + d] = val;
        }
    }

    const int b_o = tid & 7;           // batch
    const int e_o = (tid >> 3) & 7;    // local e row
    const int kq  = tid >> 6;          // k-quarter (0..3), 256 d's each
    const int eg  = g * 8 + e_o;       // global e index for this thread

    // Prefetched scalars (only threads 0..63 use them)
    float pv  = 0.0f;    // v[t][b_o][eg]
    float pgn = 0.0f;    // gate[t+1][b_o][eg]
    if (tid < 64) {
        pv  = v   [((size_t)b_o * SEQ + 0) * DIMN + eg];
        pgn = gate[((size_t)b_o * SEQ + 1) * DIMN + eg];
    }

    __syncthreads();

    for (int t = 0; t < SEQ; t++) {
        // ---- phase 1: stage blended_t into smem (t=0: zeros)
        if (t == 0) {
#pragma unroll
            for (int j = 0; j < 8; j++)
                *(float4*)&bl[j * 1028 + tid * 4] = make_float4(0.f, 0.f, 0.f, 0.f);
        } else {
            const float* src = blended + (size_t)(t & 1) * (BATCH * DIMN);
#pragma unroll
            for (int j = 0; j < 8; j++) {
                float4 s4 = __ldcg((const float4*)&src[j * DIMN + tid * 4]);
                *(float4*)&bl[j * 1028 + tid * 4] = s4;
            }
        }
        __syncthreads();

        // ---- phase 2: partial dot over this thread's 256 d's
        unsigned long long a0 = 0ull, a1 = 0ull;
        const float* ap = &As[e_o * 1028 + kq * 256];
        const float* xp = &bl[b_o * 1028 + kq * 256];
#pragma unroll 8
        for (int j = 0; j < 64; j++) {
            ulonglong2 av = *(const ulonglong2*)(ap + j * 4);
            ulonglong2 xv = *(const ulonglong2*)(xp + j * 4);
            a0 = fma2(av.x, xv.x, a0);
            a1 = fma2(av.y, xv.y, a1);
        }
        red[tid] = lo32(a0) + hi32(a0) + lo32(a1) + hi32(a1);
        __syncthreads();

        // ---- phase 3: combine, tanh, write state + next blended
        if (tid < 64) {
            float tot = red[tid] + red[tid + 64] + red[tid + 128] + red[tid + 192];
            float val = tanhf(tot + pv);
            states[((size_t)t * BATCH + b_o) * DIMN + eg] = val;
            if (t + 1 < SEQ) {
                blended[(size_t)((t + 1) & 1) * (BATCH * DIMN) + b_o * DIMN + eg]
                    = pgn * val;
            }
        }

        if (t + 1 < SEQ) {
            __syncthreads();   // blended stores issued by all producer threads

            // prefetch next step's scalars while the barrier resolves
            if (tid < 64) {
                pv  = v[((size_t)b_o * SEQ + (t + 1)) * DIMN + eg];
                pgn = (t + 2 < SEQ)
                    ? gate[((size_t)b_o * SEQ + (t + 2)) * DIMN + eg] : 0.0f;
            }

            if (tid == 0) {
                arrive_release(&g_bar);                       // release: orders stores
                const unsigned long long target =
                    (unsigned long long)(t + 1) * GBLK;
                while (ld_acquire(&g_bar) < target) {}        // acquire: orders loads
            }
            __syncthreads();
        }
    }
}

// ---------------- host launcher --------------------------------------------
extern "C" void kernel_launch(void* const* d_in, const int* in_sizes, int n_in,
                              void* d_out, int out_size)
{
    (void)in_sizes; (void)n_in; (void)out_size;

    const float* x     = (const float*)d_in[0];
    const float* A     = (const float*)d_in[1];
    const float* B     = (const float*)d_in[2];
    const float* W_in  = (const float*)d_in[3];
    const float* b_in  = (const float*)d_in[4];
    const float* W_g   = (const float*)d_in[5];
    const float* b_g   = (const float*)d_in[6];
    const float* W_out = (const float*)d_in[7];
    const float* b_out = (const float*)d_in[8];
    float* out = (float*)d_out;

    float *inp, *gate, *w, *u, *states, *blended;
    cudaGetSymbolAddress((void**)&inp,     g_inp);
    cudaGetSymbolAddress((void**)&gate,    g_gate);
    cudaGetSymbolAddress((void**)&w,       g_w);
    cudaGetSymbolAddress((void**)&u,       g_u);
    cudaGetSymbolAddress((void**)&states,  g_states);
    cudaGetSymbolAddress((void**)&blended, g_bl);

    const int scan_smem = (16 * 1028 + 256) * (int)sizeof(float);  // 66816 B
    cudaFuncSetAttribute(scan_kernel, cudaFuncAttributeMaxDynamicSharedMemorySize,
                         scan_smem);

    dim3 grid(8, 256), blk(256);

    // 1) inp = x @ W_in^T + b_in
    gemm_tn<MODE_PLAIN><<<grid, blk>>>(x, W_in, b_in, nullptr, inp, nullptr);
    // 2) u = inp @ B^T
    gemm_tn<MODE_PLAIN><<<grid, blk>>>(inp, B, nullptr, nullptr, u, nullptr);
    // 3) gate = sigmoid(inp @ W_gate^T + b_gate);  w = (1-gate)*inp
    gemm_tn<MODE_SIGW ><<<grid, blk>>>(inp, W_g, b_g, inp, gate, w);
    // 4) u += w @ A^T   (now u == v)
    gemm_tn<MODE_ADDC ><<<grid, blk>>>(w, A, nullptr, nullptr, u, nullptr);
    // 5) sequential scan
    bar_reset_kernel<<<1, 1>>>();
    scan_kernel<<<GBLK, blk, scan_smem>>>(gate, u, states, A, blended);
    // 6) out = states @ W_out^T + b_out  (permuted store to (b, s, e))
    gemm_tn<MODE_OUTP><<<grid, blk>>>(states, W_out, b_out, nullptr, out, nullptr);
}

// round 6
// speedup vs baseline: 1.5468x; 1.4736x over previous
#include <cuda_runtime.h>
#include <cstdint>
#include <math.h>

// Problem constants
#define SEQ   4096
#define BATCH 8
#define DIMN  1024
#define TOK   (SEQ * BATCH)                 // 32768 rows

// ---------------- scratch (device globals; no allocation allowed) ----------
__device__ float g_inp   [(size_t)TOK * DIMN];
__device__ float g_gate  [(size_t)TOK * DIMN];
__device__ float g_w     [(size_t)TOK * DIMN];
__device__ float g_u     [(size_t)TOK * DIMN];   // becomes v after ADDC GEMM
__device__ float g_states[(size_t)TOK * DIMN];   // [t][b][d]
__device__ float g_bl    [2 * BATCH * DIMN];     // blended, double-buffered
// one flag per CTA, each on its own 128B line (no atomic serialization)
__device__ unsigned g_flags[128 * 32];

// ---------------- f32x2 helpers (FFMA2 only reachable via PTX) -------------
__device__ __forceinline__ unsigned long long dup2(float x) {
    unsigned long long r;
    asm("mov.b64 %0, {%1, %1};" : "=l"(r) : "r"(__float_as_uint(x)));
    return r;
}
__device__ __forceinline__ unsigned long long fma2(unsigned long long a,
                                                   unsigned long long b,
                                                   unsigned long long c) {
    unsigned long long d;
    asm("fma.rn.f32x2 %0, %1, %2, %3;" : "=l"(d) : "l"(a), "l"(b), "l"(c));
    return d;
}
__device__ __forceinline__ float lo32(unsigned long long v) { return __uint_as_float((unsigned)v); }
__device__ __forceinline__ float hi32(unsigned long long v) { return __uint_as_float((unsigned)(v >> 32)); }

// ---------------- distributed-flag barrier primitives ----------------------
// release store: cumulativity via the preceding __syncthreads() CTA fence
__device__ __forceinline__ void st_release_u32(unsigned* p, unsigned v) {
    asm volatile("st.release.gpu.global.u32 [%0], %1;" :: "l"(p), "r"(v) : "memory");
}
__device__ __forceinline__ unsigned ld_acquire_u32(const unsigned* p) {
    unsigned v;
    asm volatile("ld.acquire.gpu.global.u32 %0, [%1];" : "=r"(v) : "l"(p) : "memory");
    return v;
}

// ---------------- GEMM:  C[m][n] = sum_k X[m][k] * W[n][k]  (+ epilogue) ---
// M = 32768, N = K = 1024. Tiles 128x128x16, 256 threads, 8x8 microtile.
#define MODE_PLAIN 0
#define MODE_SIGW  1   // C = sigmoid(acc+bias); C2 = (1-C)*aux   (gate & w)
#define MODE_ADDC  2   // C += acc                                (v = w@A^T + u)
#define MODE_OUTP  3   // permuted store: row m=(t*8+b) -> out[(b*SEQ+t)][n]

template <int MODE>
__global__ void __launch_bounds__(256, 2)
gemm_tn(const float* __restrict__ X, const float* __restrict__ Wm,
        const float* __restrict__ bias, const float* __restrict__ aux,
        float* __restrict__ C, float* __restrict__ C2)
{
    __shared__ float Xs[16][132];
    __shared__ float Ws[16][132];

    const int tid  = threadIdx.x;
    const int bn   = blockIdx.x;      // 0..7
    const int bm   = blockIdx.y;      // 0..255
    const int row0 = bm * 128;
    const int col0 = bn * 128;
    const int r0   = tid >> 2;        // 0..63
    const int kq   = tid & 3;         // 0..3
    const int tx   = tid & 15;
    const int ty   = tid >> 4;

    const float* xp0 = X  + (size_t)(row0 + r0)      * DIMN + kq * 4;
    const float* xp1 = X  + (size_t)(row0 + r0 + 64) * DIMN + kq * 4;
    const float* wp0 = Wm + (size_t)(col0 + r0)      * DIMN + kq * 4;
    const float* wp1 = Wm + (size_t)(col0 + r0 + 64) * DIMN + kq * 4;

    float4 xa0 = *(const float4*)xp0;
    float4 xa1 = *(const float4*)xp1;
    float4 wa0 = *(const float4*)wp0;
    float4 wa1 = *(const float4*)wp1;

    unsigned long long acc[8][4];
#pragma unroll
    for (int i = 0; i < 8; i++)
#pragma unroll
        for (int j = 0; j < 4; j++) acc[i][j] = 0ull;

    for (int kt = 0; kt < 64; kt++) {
        Xs[kq*4+0][r0]    = xa0.x; Xs[kq*4+1][r0]    = xa0.y;
        Xs[kq*4+2][r0]    = xa0.z; Xs[kq*4+3][r0]    = xa0.w;
        Xs[kq*4+0][r0+64] = xa1.x; Xs[kq*4+1][r0+64] = xa1.y;
        Xs[kq*4+2][r0+64] = xa1.z; Xs[kq*4+3][r0+64] = xa1.w;
        Ws[kq*4+0][r0]    = wa0.x; Ws[kq*4+1][r0]    = wa0.y;
        Ws[kq*4+2][r0]    = wa0.z; Ws[kq*4+3][r0]    = wa0.w;
        Ws[kq*4+0][r0+64] = wa1.x; Ws[kq*4+1][r0+64] = wa1.y;
        Ws[kq*4+2][r0+64] = wa1.z; Ws[kq*4+3][r0+64] = wa1.w;
        __syncthreads();

        if (kt < 63) {
            xa0 = *(const float4*)(xp0 + (kt + 1) * 16);
            xa1 = *(const float4*)(xp1 + (kt + 1) * 16);
            wa0 = *(const float4*)(wp0 + (kt + 1) * 16);
            wa1 = *(const float4*)(wp1 + (kt + 1) * 16);
        }

#pragma unroll
        for (int k = 0; k < 16; k++) {
            float4 a0 = *(const float4*)&Xs[k][ty * 8];
            float4 a1 = *(const float4*)&Xs[k][ty * 8 + 4];
            ulonglong2 bq0 = *(const ulonglong2*)&Ws[k][tx * 8];
            ulonglong2 bq1 = *(const ulonglong2*)&Ws[k][tx * 8 + 4];
            unsigned long long bb0 = bq0.x, bb1 = bq0.y, bb2 = bq1.x, bb3 = bq1.y;
            float aa[8] = {a0.x, a0.y, a0.z, a0.w, a1.x, a1.y, a1.z, a1.w};
#pragma unroll
            for (int mi = 0; mi < 8; mi++) {
                unsigned long long am = dup2(aa[mi]);
                acc[mi][0] = fma2(am, bb0, acc[mi][0]);
                acc[mi][1] = fma2(am, bb1, acc[mi][1]);
                acc[mi][2] = fma2(am, bb2, acc[mi][2]);
                acc[mi][3] = fma2(am, bb3, acc[mi][3]);
            }
        }
        __syncthreads();
    }

#pragma unroll
    for (int mi = 0; mi < 8; mi++) {
        const int m = row0 + ty * 8 + mi;
#pragma unroll
        for (int p = 0; p < 4; p++) {
            const int col = col0 + tx * 8 + p * 2;
            float v0 = lo32(acc[mi][p]);
            float v1 = hi32(acc[mi][p]);
            if (MODE == MODE_PLAIN) {
                if (bias) { v0 += bias[col]; v1 += bias[col + 1]; }
                *(float2*)&C[(size_t)m * DIMN + col] = make_float2(v0, v1);
            } else if (MODE == MODE_SIGW) {
                v0 += bias[col]; v1 += bias[col + 1];
                float s0 = 1.0f / (1.0f + expf(-v0));
                float s1 = 1.0f / (1.0f + expf(-v1));
                const size_t idx = (size_t)m * DIMN + col;
                *(float2*)&C[idx] = make_float2(s0, s1);
                float2 iv = *(const float2*)&aux[idx];
                *(float2*)&C2[idx] = make_float2((1.0f - s0) * iv.x, (1.0f - s1) * iv.y);
            } else if (MODE == MODE_ADDC) {
                const size_t idx = (size_t)m * DIMN + col;
                float2 old = *(const float2*)&C[idx];
                *(float2*)&C[idx] = make_float2(old.x + v0, old.y + v1);
            } else {  // MODE_OUTP
                const int tt = m >> 3, bb = m & 7;
                v0 += bias[col]; v1 += bias[col + 1];
                const size_t idx = ((size_t)bb * SEQ + tt) * DIMN + col;
                *(float2*)&C[idx] = make_float2(v0, v1);
            }
        }
    }
}

// ---------------- barrier reset (runs before scan each launch) -------------
__global__ void bar_reset_kernel() {
    int i = blockIdx.x * blockDim.x + threadIdx.x;
    if (i < 128 * 32) g_flags[i] = 0u;
}

// ---------------- persistent scan kernel -----------------------------------
// G=128 CTAs (all co-resident). CTA g owns A rows [g*8, g*8+8).
// Producer-side gating: at step t, CTA g publishes blended_{t+1} =
// gate_{t+1} * state_t for its 64 (e,b) cells into the parity-(t+1) buffer.
// Barrier: per-CTA release flag on its own 128B line; 128 poller threads
// (tid 128..255) each acquire-poll one flag in parallel.
#define GBLK 128

__global__ void __launch_bounds__(256, 1)
scan_kernel(const float* __restrict__ gate, const float* __restrict__ v,
            float* __restrict__ states, const float* __restrict__ A,
            float* __restrict__ blended)
{
    extern __shared__ float sm[];
    float* As  = sm;                 // [8][1028]
    float* bl  = sm + 8 * 1028;      // [8][1028]
    float* red = sm + 16 * 1028;     // [256]

    const int tid = threadIdx.x;
    const int g   = blockIdx.x;

    // Load this block's A slice into smem (padded rows: 1028 floats)
    {
        const float* Ap = A + (size_t)g * 8 * DIMN;
        for (int i = tid * 4; i < 8 * DIMN; i += 256 * 4) {
            const int e = i >> 10, d = i & 1023;
            float4 val = *(const float4*)&Ap[(size_t)e * DIMN + d];
            *(float4*)&As[e * 1028 + d] = val;
        }
    }

    const int b_o = tid & 7;           // batch
    const int e_o = (tid >> 3) & 7;    // local e row
    const int kq  = tid >> 6;          // k-quarter (0..3), 256 d's each
    const int eg  = g * 8 + e_o;       // global e index
    const int rot = (g * 8) & 1023;    // break L2 hot-line convoy
    const int off = (tid * 4 + rot) & 1023;

    // poller assignment (tid 128..255 -> one remote flag each)
    unsigned* myflag   = &g_flags[g * 32];
    unsigned* pollflag = (tid >= 128) ? &g_flags[(tid - 128) * 32] : nullptr;

    float pv  = 0.0f;
    float pgn = 0.0f;
    if (tid < 64) {
        pv  = v   [((size_t)b_o * SEQ + 0) * DIMN + eg];
        pgn = gate[((size_t)b_o * SEQ + 1) * DIMN + eg];
    }

    __syncthreads();

    for (int t = 0; t < SEQ; t++) {
        // ---- phase 1: stage blended_t into smem (t=0: zeros)
        if (t == 0) {
#pragma unroll
            for (int j = 0; j < 8; j++)
                *(float4*)&bl[j * 1028 + off] = make_float4(0.f, 0.f, 0.f, 0.f);
        } else {
            const float* src = blended + (size_t)(t & 1) * (BATCH * DIMN);
#pragma unroll
            for (int j = 0; j < 8; j++) {
                float4 s4 = __ldcg((const float4*)&src[j * DIMN + off]);
                *(float4*)&bl[j * 1028 + off] = s4;
            }
        }
        __syncthreads();

        // ---- phase 2: partial dot over this thread's 256 d's
        unsigned long long a0 = 0ull, a1 = 0ull;
        const float* ap = &As[e_o * 1028 + kq * 256];
        const float* xp = &bl[b_o * 1028 + kq * 256];
#pragma unroll 8
        for (int j = 0; j < 64; j++) {
            ulonglong2 av = *(const ulonglong2*)(ap + j * 4);
            ulonglong2 xv = *(const ulonglong2*)(xp + j * 4);
            a0 = fma2(av.x, xv.x, a0);
            a1 = fma2(av.y, xv.y, a1);
        }
        red[tid] = lo32(a0) + hi32(a0) + lo32(a1) + hi32(a1);
        __syncthreads();

        // ---- phase 3: combine, tanh, write state + next blended
        if (tid < 64) {
            float tot = red[tid] + red[tid + 64] + red[tid + 128] + red[tid + 192];
            float val = tanhf(tot + pv);
            states[((size_t)t * BATCH + b_o) * DIMN + eg] = val;
            if (t + 1 < SEQ)
                blended[(size_t)((t + 1) & 1) * (BATCH * DIMN) + b_o * DIMN + eg]
                    = pgn * val;
        }

        if (t + 1 < SEQ) {
            __syncthreads();   // CTA fence: blended stores visible (cumulativity)

            // announce our arrival (plain release store, own 128B line)
            if (tid == 0) st_release_u32(myflag, (unsigned)(t + 1));

            // prefetch next step's scalars while pollers spin
            if (tid < 64) {
                pv  = v[((size_t)b_o * SEQ + (t + 1)) * DIMN + eg];
                pgn = (t + 2 < SEQ)
                    ? gate[((size_t)b_o * SEQ + (t + 2)) * DIMN + eg] : 0.0f;
            }

            // 128 parallel pollers, one flag each
            if (tid >= 128) {
                const unsigned tgt = (unsigned)(t + 1);
                while (ld_acquire_u32(pollflag) < tgt) {}
            }
            __syncthreads();
        }
    }
}

// ---------------- host launcher --------------------------------------------
extern "C" void kernel_launch(void* const* d_in, const int* in_sizes, int n_in,
                              void* d_out, int out_size)
{
    (void)in_sizes; (void)n_in; (void)out_size;

    const float* x     = (const float*)d_in[0];
    const float* A     = (const float*)d_in[1];
    const float* B     = (const float*)d_in[2];
    const float* W_in  = (const float*)d_in[3];
    const float* b_in  = (const float*)d_in[4];
    const float* W_g   = (const float*)d_in[5];
    const float* b_g   = (const float*)d_in[6];
    const float* W_out = (const float*)d_in[7];
    const float* b_out = (const float*)d_in[8];
    float* out = (float*)d_out;

    float *inp, *gate, *w, *u, *states, *blended;
    cudaGetSymbolAddress((void**)&inp,     g_inp);
    cudaGetSymbolAddress((void**)&gate,    g_gate);
    cudaGetSymbolAddress((void**)&w,       g_w);
    cudaGetSymbolAddress((void**)&u,       g_u);
    cudaGetSymbolAddress((void**)&states,  g_states);
    cudaGetSymbolAddress((void**)&blended, g_bl);

    const int scan_smem = (16 * 1028 + 256) * (int)sizeof(float);  // 66816 B
    cudaFuncSetAttribute(scan_kernel, cudaFuncAttributeMaxDynamicSharedMemorySize,
                         scan_smem);

    dim3 grid(8, 256), blk(256);

    // 1) inp = x @ W_in^T + b_in
    gemm_tn<MODE_PLAIN><<<grid, blk>>>(x, W_in, b_in, nullptr, inp, nullptr);
    // 2) u = inp @ B^T
    gemm_tn<MODE_PLAIN><<<grid, blk>>>(inp, B, nullptr, nullptr, u, nullptr);
    // 3) gate = sigmoid(inp @ W_gate^T + b_gate);  w = (1-gate)*inp
    gemm_tn<MODE_SIGW ><<<grid, blk>>>(inp, W_g, b_g, inp, gate, w);
    // 4) u += w @ A^T   (now u == v)
    gemm_tn<MODE_ADDC ><<<grid, blk>>>(w, A, nullptr, nullptr, u, nullptr);
    // 5) sequential scan
    bar_reset_kernel<<<16, 256>>>();
    scan_kernel<<<GBLK, blk, scan_smem>>>(gate, u, states, A, blended);
    // 6) out = states @ W_out^T + b_out  (permuted store to (b, s, e))
    gemm_tn<MODE_OUTP><<<grid, blk>>>(states, W_out, b_out, nullptr, out, nullptr);
}

// round 10
// speedup vs baseline: 1.7428x; 1.1267x over previous
#include <cuda_runtime.h>
#include <cuda_fp16.h>
#include <mma.h>
#include <cstdint>
#include <math.h>

using namespace nvcuda;

// Problem constants
#define SEQ   4096
#define BATCH 8
#define DIMN  1024
#define TOK   (SEQ * BATCH)                 // 32768 rows

// ---------------- scratch (device globals; no allocation allowed) ----------
__device__ float g_inp [(size_t)TOK * DIMN];
__device__ float g_gate[(size_t)TOK * DIMN];
__device__ float g_u   [(size_t)TOK * DIMN];    // becomes v after ADDC GEMM
__device__ float g_bl  [2 * BATCH * DIMN];      // blended, double-buffered
__device__ unsigned g_flags[128 * 32];          // per-CTA flag, own 128B line

// fp16 hi/lo split operands
__device__ __half g_xhi[(size_t)TOK * DIMN], g_xlo[(size_t)TOK * DIMN];
__device__ __half g_ihi[(size_t)TOK * DIMN], g_ilo[(size_t)TOK * DIMN];
__device__ __half g_whi[(size_t)TOK * DIMN], g_wlo[(size_t)TOK * DIMN];
__device__ __half g_shi[(size_t)TOK * DIMN], g_slo[(size_t)TOK * DIMN];
__device__ __half g_Winh[DIMN * DIMN], g_Winl[DIMN * DIMN];
__device__ __half g_Bh  [DIMN * DIMN], g_Bl  [DIMN * DIMN];
__device__ __half g_Wgh [DIMN * DIMN], g_Wgl [DIMN * DIMN];
__device__ __half g_Ah  [DIMN * DIMN], g_Al  [DIMN * DIMN];
__device__ __half g_Woh [DIMN * DIMN], g_Wol [DIMN * DIMN];

// ---------------- f32x2 helpers (scan dot) ---------------------------------
__device__ __forceinline__ unsigned long long fma2(unsigned long long a,
                                                   unsigned long long b,
                                                   unsigned long long c) {
    unsigned long long d;
    asm("fma.rn.f32x2 %0, %1, %2, %3;" : "=l"(d) : "l"(a), "l"(b), "l"(c));
    return d;
}
__device__ __forceinline__ float lo32(unsigned long long v) { return __uint_as_float((unsigned)v); }
__device__ __forceinline__ float hi32(unsigned long long v) { return __uint_as_float((unsigned)(v >> 32)); }

// ---------------- distributed-flag barrier primitives ----------------------
__device__ __forceinline__ void st_release_u32(unsigned* p, unsigned v) {
    asm volatile("st.release.gpu.global.u32 [%0], %1;" :: "l"(p), "r"(v) : "memory");
}
__device__ __forceinline__ unsigned ld_acquire_u32(const unsigned* p) {
    unsigned v;
    asm volatile("ld.acquire.gpu.global.u32 %0, [%1];" : "=r"(v) : "l"(p) : "memory");
    return v;
}

// ---------------- fp16 hi/lo split helpers ---------------------------------
__device__ __forceinline__ void split4h(float4 v, __half* hi, __half* lo) {
    __half h0 = __float2half_rn(v.x), h1 = __float2half_rn(v.y);
    __half h2 = __float2half_rn(v.z), h3 = __float2half_rn(v.w);
    __half l0 = __float2half_rn(v.x - __half2float(h0));
    __half l1 = __float2half_rn(v.y - __half2float(h1));
    __half l2 = __float2half_rn(v.z - __half2float(h2));
    __half l3 = __float2half_rn(v.w - __half2float(h3));
    ((__half2*)hi)[0] = __halves2half2(h0, h1);
    ((__half2*)hi)[1] = __halves2half2(h2, h3);
    ((__half2*)lo)[0] = __halves2half2(l0, l1);
    ((__half2*)lo)[1] = __halves2half2(l2, l3);
}

__global__ void conv_split(const float* __restrict__ s, __half* __restrict__ hi,
                           __half* __restrict__ lo, int n4) {
    int i = blockIdx.x * blockDim.x + threadIdx.x;
    if (i >= n4) return;
    float4 v = ((const float4*)s)[i];
    split4h(v, hi + (size_t)i * 4, lo + (size_t)i * 4);
}

// ---------------- wmma GEMM:  C[m][n] = sum_k X[m][k] * W[n][k] ------------
// fp16 2-word split, 3 products (hh, hl, lh), fp32 accumulate.
// CTA tile 128x128, K-chunk 16, 8 warps (warp tile 64x32), double-buffered.
#define MODE_PLAIN  0
#define MODE_PSPLIT 1   // C fp32 + Chi/Clo fp16 split            (inp)
#define MODE_SIGW   2   // C = sigmoid(acc+bias); Chi/Clo = split((1-C)*aux)
#define MODE_ADDC   3   // C += acc
#define MODE_OUTP   4   // permuted: row m=(t*8+b) -> out[(b*SEQ+t)][n]

#define SLD      24                     // smem ld (halves) per row, padded
#define MAT_B    (128 * SLD * 2)        // 6144 B, one 128x16 fp16 matrix
#define STAGE_B  (4 * MAT_B)            // Ahi,Alo,Bhi,Blo = 24576 B
#define CS_LD    132
#define GSM      (128 * CS_LD * 4)      // 67584 B (>= 2*STAGE_B)

template <int MODE>
__global__ void __launch_bounds__(256, 1)
gemm_wm(const __half* __restrict__ Xhi, const __half* __restrict__ Xlo,
        const __half* __restrict__ Whi, const __half* __restrict__ Wlo,
        const float* __restrict__ bias, const float* __restrict__ aux,
        float* __restrict__ C, __half* __restrict__ Chi, __half* __restrict__ Clo)
{
    extern __shared__ char dyn[];

    const int tid  = threadIdx.x;
    const int wid  = tid >> 5;
    const int row0 = blockIdx.y * 128;   // m
    const int col0 = blockIdx.x * 128;   // n

    // -------- global load staging: thread -> (row r, 16B half h) ----------
    const int r = tid >> 1;              // 0..127
    const int h = tid & 1;               // 0..1
    const __half* gp[4] = {
        Xhi + (size_t)(row0 + r) * DIMN + h * 8,
        Xlo + (size_t)(row0 + r) * DIMN + h * 8,
        Whi + (size_t)(col0 + r) * DIMN + h * 8,
        Wlo + (size_t)(col0 + r) * DIMN + h * 8 };
    uint4 rg[4];

    auto gload = [&](int kc) {
#pragma unroll
        for (int q = 0; q < 4; q++)
            rg[q] = *(const uint4*)(gp[q] + kc * 16);
    };
    auto sstore = [&](int st) {
        char* sb = dyn + st * STAGE_B + r * (SLD * 2) + h * 16;
#pragma unroll
        for (int q = 0; q < 4; q++)
            *(uint4*)(sb + q * MAT_B) = rg[q];
    };

    // -------- wmma fragments ---------------------------------------------
    const int wm = wid & 1;              // 0..1 : 64 m-rows
    const int wn = wid >> 1;             // 0..3 : 32 n-cols
    wmma::fragment<wmma::accumulator, 16, 16, 16, float> acc[4][2];
#pragma unroll
    for (int mi = 0; mi < 4; mi++)
#pragma unroll
        for (int ni = 0; ni < 2; ni++) wmma::fill_fragment(acc[mi][ni], 0.0f);

    gload(0);
    sstore(0);

    for (int kc = 0; kc < 64; kc++) {
        const int cur = kc & 1;
        __syncthreads();                 // stage cur ready; prev readers done
        if (kc < 63) gload(kc + 1);

        const __half* sA_h = (const __half*)(dyn + cur * STAGE_B);
        const __half* sA_l = (const __half*)(dyn + cur * STAGE_B + MAT_B);
        const __half* sB_h = (const __half*)(dyn + cur * STAGE_B + 2 * MAT_B);
        const __half* sB_l = (const __half*)(dyn + cur * STAGE_B + 3 * MAT_B);

        wmma::fragment<wmma::matrix_a, 16, 16, 16, __half, wmma::row_major> fa_h[4], fa_l[4];
#pragma unroll
        for (int mi = 0; mi < 4; mi++) {
            wmma::load_matrix_sync(fa_h[mi], sA_h + (wm * 64 + mi * 16) * SLD, SLD);
            wmma::load_matrix_sync(fa_l[mi], sA_l + (wm * 64 + mi * 16) * SLD, SLD);
        }
#pragma unroll
        for (int ni = 0; ni < 2; ni++) {
            wmma::fragment<wmma::matrix_b, 16, 16, 16, __half, wmma::col_major> fb_h, fb_l;
            wmma::load_matrix_sync(fb_h, sB_h + (wn * 32 + ni * 16) * SLD, SLD);
            wmma::load_matrix_sync(fb_l, sB_l + (wn * 32 + ni * 16) * SLD, SLD);
#pragma unroll
            for (int mi = 0; mi < 4; mi++) {
                wmma::mma_sync(acc[mi][ni], fa_h[mi], fb_h, acc[mi][ni]);
                wmma::mma_sync(acc[mi][ni], fa_h[mi], fb_l, acc[mi][ni]);
                wmma::mma_sync(acc[mi][ni], fa_l[mi], fb_h, acc[mi][ni]);
            }
        }

        if (kc < 63) sstore((kc + 1) & 1);
    }
    __syncthreads();                     // all compute done; reuse smem as Cs

    // -------- stage accumulators to smem ----------------------------------
    float* Cs = (float*)dyn;
#pragma unroll
    for (int mi = 0; mi < 4; mi++)
#pragma unroll
        for (int ni = 0; ni < 2; ni++)
            wmma::store_matrix_sync(&Cs[(wm * 64 + mi * 16) * CS_LD + wn * 32 + ni * 16],
                                    acc[mi][ni], CS_LD, wmma::mem_row_major);
    __syncthreads();

    // -------- epilogue: thread -> 8 rows x 8 cols -------------------------
    const int tx = tid & 15;             // col group
    const int ty = tid >> 4;             // row group
#pragma unroll
    for (int mi = 0; mi < 8; mi++) {
        const int lm = ty * 8 + mi;
        const int m  = row0 + lm;
#pragma unroll
        for (int q = 0; q < 2; q++) {
            const int lc = tx * 8 + q * 4;
            const int n  = col0 + lc;
            float4 a = *(const float4*)&Cs[lm * CS_LD + lc];
            if (MODE == MODE_PLAIN) {
                *(float4*)&C[(size_t)m * DIMN + n] = a;
            } else if (MODE == MODE_PSPLIT) {
                float4 bv = *(const float4*)&bias[n];
                a.x += bv.x; a.y += bv.y; a.z += bv.z; a.w += bv.w;
                const size_t idx = (size_t)m * DIMN + n;
                *(float4*)&C[idx] = a;
                split4h(a, Chi + idx, Clo + idx);
            } else if (MODE == MODE_SIGW) {
                float4 bv = *(const float4*)&bias[n];
                float s0 = 1.0f / (1.0f + expf(-(a.x + bv.x)));
                float s1 = 1.0f / (1.0f + expf(-(a.y + bv.y)));
                float s2 = 1.0f / (1.0f + expf(-(a.z + bv.z)));
                float s3 = 1.0f / (1.0f + expf(-(a.w + bv.w)));
                const size_t idx = (size_t)m * DIMN + n;
                *(float4*)&C[idx] = make_float4(s0, s1, s2, s3);
                float4 iv = *(const float4*)&aux[idx];
                float4 wv = make_float4((1.0f - s0) * iv.x, (1.0f - s1) * iv.y,
                                        (1.0f - s2) * iv.z, (1.0f - s3) * iv.w);
                split4h(wv, Chi + idx, Clo + idx);
            } else if (MODE == MODE_ADDC) {
                const size_t idx = (size_t)m * DIMN + n;
                float4 o = *(const float4*)&C[idx];
                *(float4*)&C[idx] = make_float4(o.x + a.x, o.y + a.y,
                                                o.z + a.z, o.w + a.w);
            } else {  // MODE_OUTP
                float4 bv = *(const float4*)&bias[n];
                const int tt = m >> 3, bb = m & 7;
                *(float4*)&C[((size_t)bb * SEQ + tt) * DIMN + n] =
                    make_float4(a.x + bv.x, a.y + bv.y, a.z + bv.z, a.w + bv.w);
            }
        }
    }
}

// ---------------- barrier reset --------------------------------------------
__global__ void bar_reset_kernel() {
    int i = blockIdx.x * blockDim.x + threadIdx.x;
    if (i < 128 * 32) g_flags[i] = 0u;
}

// ---------------- persistent scan kernel (round-6 structure) ---------------
#define GBLK 128

__global__ void __launch_bounds__(256, 1)
scan_kernel(const float* __restrict__ gate, const float* __restrict__ v,
            const float* __restrict__ A, float* __restrict__ blended,
            __half* __restrict__ shi, __half* __restrict__ slo)
{
    extern __shared__ float sm[];
    float* As  = sm;                 // [8][1028]
    float* bl  = sm + 8 * 1028;      // [8][1028]
    float* red = sm + 16 * 1028;     // [256]

    const int tid = threadIdx.x;
    const int g   = blockIdx.x;

    {
        const float* Ap = A + (size_t)g * 8 * DIMN;
        for (int i = tid * 4; i < 8 * DIMN; i += 256 * 4) {
            const int e = i >> 10, d = i & 1023;
            float4 val = *(const float4*)&Ap[(size_t)e * DIMN + d];
            *(float4*)&As[e * 1028 + d] = val;
        }
    }

    const int b_o = tid & 7;
    const int e_o = (tid >> 3) & 7;
    const int kq  = tid >> 6;
    const int eg  = g * 8 + e_o;
    const int rot = (g * 8) & 1023;
    const int off = (tid * 4 + rot) & 1023;

    unsigned* myflag   = &g_flags[g * 32];
    unsigned* pollflag = (tid >= 128) ? &g_flags[(tid - 128) * 32] : nullptr;

    float pv  = 0.0f;
    float pgn = 0.0f;
    if (tid < 64) {
        pv  = v   [((size_t)b_o * SEQ + 0) * DIMN + eg];
        pgn = gate[((size_t)b_o * SEQ + 1) * DIMN + eg];
    }

    __syncthreads();

    for (int t = 0; t < SEQ; t++) {
        if (t == 0) {
#pragma unroll
            for (int j = 0; j < 8; j++)
                *(float4*)&bl[j * 1028 + off] = make_float4(0.f, 0.f, 0.f, 0.f);
        } else {
            const float* src = blended + (size_t)(t & 1) * (BATCH * DIMN);
#pragma unroll
            for (int j = 0; j < 8; j++) {
                float4 s4 = __ldcg((const float4*)&src[j * DIMN + off]);
                *(float4*)&bl[j * 1028 + off] = s4;
            }
        }
        __syncthreads();

        unsigned long long a0 = 0ull, a1 = 0ull;
        const float* ap = &As[e_o * 1028 + kq * 256];
        const float* xp = &bl[b_o * 1028 + kq * 256];
#pragma unroll 8
        for (int j = 0; j < 64; j++) {
            ulonglong2 av = *(const ulonglong2*)(ap + j * 4);
            ulonglong2 xv = *(const ulonglong2*)(xp + j * 4);
            a0 = fma2(av.x, xv.x, a0);
            a1 = fma2(av.y, xv.y, a1);
        }
        red[tid] = lo32(a0) + hi32(a0) + lo32(a1) + hi32(a1);
        __syncthreads();

        if (tid < 64) {
            float tot = red[tid] + red[tid + 64] + red[tid + 128] + red[tid + 192];
            float val = tanhf(tot + pv);
            const size_t sidx = ((size_t)t * BATCH + b_o) * DIMN + eg;
            __half hv = __float2half_rn(val);
            shi[sidx] = hv;
            slo[sidx] = __float2half_rn(val - __half2float(hv));
            if (t + 1 < SEQ)
                blended[(size_t)((t + 1) & 1) * (BATCH * DIMN) + b_o * DIMN + eg]
                    = pgn * val;
        }

        if (t + 1 < SEQ) {
            __syncthreads();   // CTA fence: blended stores visible

            if (tid == 0) st_release_u32(myflag, (unsigned)(t + 1));

            if (tid < 64) {
                pv  = v[((size_t)b_o * SEQ + (t + 1)) * DIMN + eg];
                pgn = (t + 2 < SEQ)
                    ? gate[((size_t)b_o * SEQ + (t + 2)) * DIMN + eg] : 0.0f;
            }

            if (tid >= 128) {
                const unsigned tgt = (unsigned)(t + 1);
                while (ld_acquire_u32(pollflag) < tgt) {}
            }
            __syncthreads();
        }
    }
}

// ---------------- host launcher --------------------------------------------
extern "C" void kernel_launch(void* const* d_in, const int* in_sizes, int n_in,
                              void* d_out, int out_size)
{
    (void)in_sizes; (void)n_in; (void)out_size;

    const float* x     = (const float*)d_in[0];
    const float* A     = (const float*)d_in[1];
    const float* B     = (const float*)d_in[2];
    const float* W_in  = (const float*)d_in[3];
    const float* b_in  = (const float*)d_in[4];
    const float* W_g   = (const float*)d_in[5];
    const float* b_g   = (const float*)d_in[6];
    const float* W_out = (const float*)d_in[7];
    const float* b_out = (const float*)d_in[8];
    float* out = (float*)d_out;

    float *inp, *gate, *u, *blended;
    cudaGetSymbolAddress((void**)&inp,     g_inp);
    cudaGetSymbolAddress((void**)&gate,    g_gate);
    cudaGetSymbolAddress((void**)&u,       g_u);
    cudaGetSymbolAddress((void**)&blended, g_bl);

    __half *xhi,*xlo,*ihi,*ilo,*whi,*wlo,*shi,*slo;
    __half *Winh,*Winl,*Bh,*Bl,*Wgh,*Wgl,*Ah,*Al,*Woh,*Wol;
    cudaGetSymbolAddress((void**)&xhi, g_xhi);  cudaGetSymbolAddress((void**)&xlo, g_xlo);
    cudaGetSymbolAddress((void**)&ihi, g_ihi);  cudaGetSymbolAddress((void**)&ilo, g_ilo);
    cudaGetSymbolAddress((void**)&whi, g_whi);  cudaGetSymbolAddress((void**)&wlo, g_wlo);
    cudaGetSymbolAddress((void**)&shi, g_shi);  cudaGetSymbolAddress((void**)&slo, g_slo);
    cudaGetSymbolAddress((void**)&Winh, g_Winh); cudaGetSymbolAddress((void**)&Winl, g_Winl);
    cudaGetSymbolAddress((void**)&Bh,   g_Bh);   cudaGetSymbolAddress((void**)&Bl,   g_Bl);
    cudaGetSymbolAddress((void**)&Wgh,  g_Wgh);  cudaGetSymbolAddress((void**)&Wgl,  g_Wgl);
    cudaGetSymbolAddress((void**)&Ah,   g_Ah);   cudaGetSymbolAddress((void**)&Al,   g_Al);
    cudaGetSymbolAddress((void**)&Woh,  g_Woh);  cudaGetSymbolAddress((void**)&Wol,  g_Wol);

    const int scan_smem = (16 * 1028 + 256) * (int)sizeof(float);  // 66816 B
    cudaFuncSetAttribute(scan_kernel, cudaFuncAttributeMaxDynamicSharedMemorySize, scan_smem);
    cudaFuncSetAttribute(gemm_wm<MODE_PLAIN>,  cudaFuncAttributeMaxDynamicSharedMemorySize, GSM);
    cudaFuncSetAttribute(gemm_wm<MODE_PSPLIT>, cudaFuncAttributeMaxDynamicSharedMemorySize, GSM);
    cudaFuncSetAttribute(gemm_wm<MODE_SIGW>,   cudaFuncAttributeMaxDynamicSharedMemorySize, GSM);
    cudaFuncSetAttribute(gemm_wm<MODE_ADDC>,   cudaFuncAttributeMaxDynamicSharedMemorySize, GSM);
    cudaFuncSetAttribute(gemm_wm<MODE_OUTP>,   cudaFuncAttributeMaxDynamicSharedMemorySize, GSM);

    // 0) fp16 hi/lo conversions (x + 5 weight matrices)
    conv_split<<<(TOK * DIMN / 4 + 255) / 256, 256>>>(x, xhi, xlo, TOK * DIMN / 4);
    const int w4 = DIMN * DIMN / 4;
    conv_split<<<(w4 + 255) / 256, 256>>>(W_in,  Winh, Winl, w4);
    conv_split<<<(w4 + 255) / 256, 256>>>(B,     Bh,   Bl,   w4);
    conv_split<<<(w4 + 255) / 256, 256>>>(W_g,   Wgh,  Wgl,  w4);
    conv_split<<<(w4 + 255) / 256, 256>>>(A,     Ah,   Al,   w4);
    conv_split<<<(w4 + 255) / 256, 256>>>(W_out, Woh,  Wol,  w4);

    dim3 grid(8, 256), blk(256);
    // 1) inp = x @ W_in^T + b_in  (+ fp16 split of inp)
    gemm_wm<MODE_PSPLIT><<<grid, blk, GSM>>>(xhi, xlo, Winh, Winl, b_in, nullptr, inp, ihi, ilo);
    // 2) u = inp @ B^T
    gemm_wm<MODE_PLAIN ><<<grid, blk, GSM>>>(ihi, ilo, Bh, Bl, nullptr, nullptr, u, nullptr, nullptr);
    // 3) gate = sigmoid(inp @ Wg^T + b_g);  w = (1-gate)*inp (fp16 split)
    gemm_wm<MODE_SIGW  ><<<grid, blk, GSM>>>(ihi, ilo, Wgh, Wgl, b_g, inp, gate, whi, wlo);
    // 4) u += w @ A^T   (now u == v)
    gemm_wm<MODE_ADDC  ><<<grid, blk, GSM>>>(whi, wlo, Ah, Al, nullptr, nullptr, u, nullptr, nullptr);
    // 5) sequential scan (emits states as fp16 hi/lo)
    bar_reset_kernel<<<16, 256>>>();
    scan_kernel<<<GBLK, blk, scan_smem>>>(gate, u, A, blended, shi, slo);
    // 6) out = states @ W_out^T + b_out  (permuted store)
    gemm_wm<MODE_OUTP  ><<<grid, blk, GSM>>>(shi, slo, Woh, Wol, b_out, nullptr, out, nullptr, nullptr);
}